// round 15
// baseline (speedup 1.0000x reference)
#include <cuda_runtime.h>
#include <cuda_bf16.h>
#include <cuda_fp8.h>

#define MAXN 65536
#define MAXE 1048576
#define C 64

// -------- scratch (static device globals; no allocation) --------
__device__ __align__(16) unsigned g_xb [(size_t)MAXN * 64];  // x, bf16 packed pairs (GEMM input)
__device__ __align__(16) unsigned g_x8 [(size_t)MAXN * 32];  // x, fp8 e4m3 x4 (aggr gather)
__device__ __align__(16) unsigned g_a1b[(size_t)MAXN * 64];  // aggr(x), bf16
__device__ __align__(16) unsigned g_hb [(size_t)MAXN * 64];  // h, bf16
__device__ __align__(16) unsigned g_ub [(size_t)MAXN * 32];  // u_l, bf16 (64 wide)
__device__ __align__(16) float    g_ur [(size_t)MAXN * C];   // u_r, fp32
__device__ int g_counts[MAXN];
__device__ int g_offsets[MAXN];
__device__ int g_rank[MAXE];          // within-bucket rank of each edge
__device__ int g_src_sorted[MAXE];
__device__ __align__(16) unsigned g_zeroed[4];   // [0..1]=acc(float), [2]=total, [3]=done

__device__ __forceinline__ unsigned pack_bf2(float a, float b) {
    __nv_bfloat162 p = __floats2bfloat162_rn(a, b);
    return *reinterpret_cast<unsigned*>(&p);
}
__device__ __forceinline__ float2 unpack_bf2(unsigned w) {
    return __bfloat1622float2(*reinterpret_cast<__nv_bfloat162*>(&w));
}
__device__ __forceinline__ float2 fp8x2_to_f2(unsigned short v) {
    __half2_raw hr = __nv_cvt_fp8x2_to_halfraw2((__nv_fp8x2_storage_t)v, __NV_E4M3);
    return __half22float2(*reinterpret_cast<__half2*>(&hr));
}

__device__ __forceinline__ void mma_bf16(float c[4], const unsigned a[4], const unsigned b[2]) {
    asm volatile(
        "mma.sync.aligned.m16n8k16.row.col.f32.bf16.bf16.f32 "
        "{%0,%1,%2,%3}, {%4,%5,%6,%7}, {%8,%9}, {%0,%1,%2,%3};"
        : "+f"(c[0]), "+f"(c[1]), "+f"(c[2]), "+f"(c[3])
        : "r"(a[0]), "r"(a[1]), "r"(a[2]), "r"(a[3]), "r"(b[0]), "r"(b[1]));
}

// -------- x -> bf16 (GEMM path) + fp8 (aggr gather path); runs on side stream --------
__global__ void k_x2bf(const float4* __restrict__ x, int nwords4) {
    int i = blockIdx.x * blockDim.x + threadIdx.x;
    if (i < nwords4) {
        float4 v = x[i];
        ((uint2*)g_xb)[i] = make_uint2(pack_bf2(v.x, v.y), pack_bf2(v.z, v.w));
        unsigned lo = (unsigned)__nv_cvt_float2_to_fp8x2(make_float2(v.x, v.y),
                                                         __NV_SATFINITE, __NV_E4M3);
        unsigned hi = (unsigned)__nv_cvt_float2_to_fp8x2(make_float2(v.z, v.w),
                                                         __NV_SATFINITE, __NV_E4M3);
        g_x8[i] = lo | (hi << 16);
    }
}

// -------- histogram; the atomic's return value IS the edge's bucket rank --------
__global__ void k_hist(const int* __restrict__ dst, int e) {
    int i = blockIdx.x * blockDim.x + threadIdx.x;
    if (i < e) {
        int d = dst[i];
        g_rank[i] = atomicAdd(&g_counts[d], 1);
    }
}

// -------- offsets via warp scan + one atomic per warp --------
__global__ void k_offsets(int n) {
    int i = blockIdx.x * blockDim.x + threadIdx.x;
    int lane = threadIdx.x & 31;
    int c = (i < n) ? g_counts[i] : 0;
    int s = c;
#pragma unroll
    for (int o = 1; o < 32; o <<= 1) {
        int t = __shfl_up_sync(0xffffffffu, s, o);
        if (lane >= o) s += t;
    }
    int total = __shfl_sync(0xffffffffu, s, 31);
    int base = 0;
    if (lane == 31) base = atomicAdd((int*)&g_zeroed[2], total);
    base = __shfl_sync(0xffffffffu, base, 31);
    if (i < n) g_offsets[i] = base + s - c;
}

// -------- atomic-free scatter: position = offset[dst] + rank --------
__global__ void k_scatter(const int* __restrict__ src, const int* __restrict__ dst, int e) {
    int i = blockIdx.x * blockDim.x + threadIdx.x;
    if (i < e) {
        int d = dst[i];
        g_src_sorted[g_offsets[d] + g_rank[i]] = src[i];
    }
}

// -------- aggregation 1: mean of fp8 x rows -> bf16 (warp per node) --------
__global__ void __launch_bounds__(256) k_aggr_bf(int n) {
    int w    = (blockIdx.x * blockDim.x + threadIdx.x) >> 5;
    int lane = threadIdx.x & 31;
    if (w >= n) return;
    int start = g_offsets[w];
    int cnt   = g_counts[w];
    float4 acc = make_float4(0.f, 0.f, 0.f, 0.f);
    for (int i = 0; i < cnt; i++) {
        int s = g_src_sorted[start + i];
        unsigned v = g_x8[(size_t)s * 32 + lane];
        float2 f0 = fp8x2_to_f2((unsigned short)(v & 0xffffu));
        float2 f1 = fp8x2_to_f2((unsigned short)(v >> 16));
        acc.x += f0.x; acc.y += f0.y; acc.z += f1.x; acc.w += f1.y;
    }
    float inv = 1.0f / fmaxf((float)cnt, 1.0f);
    ((uint2*)(g_a1b + (size_t)w * 64))[lane] =
        make_uint2(pack_bf2(acc.x * inv, acc.y * inv), pack_bf2(acc.z * inv, acc.w * inv));
}

// ======== bf16 tensor-core GEMM, layer 1 ========
#define SWS 136   // sW word stride
#define SAS 68    // sA word stride

__global__ void __launch_bounds__(256) k_gemm1(const float* __restrict__ Wl,
                                               const float* __restrict__ Wr,
                                               const float* __restrict__ bias,
                                               int n) {
    extern __shared__ unsigned smem[];
    unsigned* sW = smem;                  // 128 word-rows x SWS
    unsigned* sA = smem + 128 * SWS;      // 128 rows x SAS

    int tid = threadIdx.x;
    for (int i = tid; i < 128 * 128; i += 256) {
        int k2 = i >> 7, nn = i & 127;
        const float* W = (k2 < 64) ? Wl : Wr;
        int kk = (k2 & 63) * 2;
        sW[k2 * SWS + nn] = pack_bf2(W[kk * 128 + nn], W[(kk + 1) * 128 + nn]);
    }

    int node0 = blockIdx.x * 128;
    int wid = tid >> 5, lane = tid & 31;
    int gid = lane >> 2, tig = lane & 3;
    int wm = wid >> 2, wn = wid & 3;

    float acc[4][4][4];
#pragma unroll
    for (int mi = 0; mi < 4; mi++)
#pragma unroll
        for (int ni = 0; ni < 4; ni++)
#pragma unroll
            for (int r = 0; r < 4; r++) acc[mi][ni][r] = 0.f;

#pragma unroll
    for (int phase = 0; phase < 2; phase++) {
        const uint2* src = (const uint2*)(phase == 0 ? g_a1b : g_xb);
        __syncthreads();
        for (int i = tid; i < 128 * 32; i += 256) {
            int r = i >> 5, c2 = i & 31;
            int node = node0 + r;
            uint2 v = make_uint2(0u, 0u);
            if (node < n) v = src[(size_t)node * 32 + c2];
            sA[r * SAS + c2 * 2]     = v.x;
            sA[r * SAS + c2 * 2 + 1] = v.y;
        }
        __syncthreads();

        int kw0 = phase * 64;
#pragma unroll
        for (int s = 0; s < 8; s++) {
            int kw = s * 8;
            unsigned afr[4][4];
#pragma unroll
            for (int mi = 0; mi < 4; mi++) {
                int m = wm * 64 + mi * 16;
                afr[mi][0] = sA[(m + gid) * SAS + kw + tig];
                afr[mi][1] = sA[(m + gid + 8) * SAS + kw + tig];
                afr[mi][2] = sA[(m + gid) * SAS + kw + 4 + tig];
                afr[mi][3] = sA[(m + gid + 8) * SAS + kw + 4 + tig];
            }
            unsigned bfr[4][2];
#pragma unroll
            for (int ni = 0; ni < 4; ni++) {
                int nc = wn * 32 + ni * 8;
                bfr[ni][0] = sW[(kw0 + kw + tig) * SWS + nc + gid];
                bfr[ni][1] = sW[(kw0 + kw + 4 + tig) * SWS + nc + gid];
            }
#pragma unroll
            for (int mi = 0; mi < 4; mi++)
#pragma unroll
                for (int ni = 0; ni < 4; ni++)
                    mma_bf16(acc[mi][ni], afr[mi], bfr[ni]);
        }
    }

    // epilogue: bias + relu -> bf16 packed h
#pragma unroll
    for (int mi = 0; mi < 4; mi++) {
#pragma unroll
        for (int ni = 0; ni < 4; ni++) {
            int m = node0 + wm * 64 + mi * 16;
            int col = wn * 32 + ni * 8 + 2 * tig;
            float bv0 = bias[col], bv1 = bias[col + 1];
            int r0 = m + gid, r1 = m + gid + 8;
            int wrd = col >> 1;
            if (r0 < n)
                g_hb[(size_t)r0 * 64 + wrd] = pack_bf2(fmaxf(acc[mi][ni][0] + bv0, 0.f),
                                                       fmaxf(acc[mi][ni][1] + bv1, 0.f));
            if (r1 < n)
                g_hb[(size_t)r1 * 64 + wrd] = pack_bf2(fmaxf(acc[mi][ni][2] + bv0, 0.f),
                                                       fmaxf(acc[mi][ni][3] + bv1, 0.f));
        }
    }
}

// ======== bf16 GEMM, layer 2: u = h @ [W2l | W2r] ========
__global__ void __launch_bounds__(256) k_gemm2(const float* __restrict__ Wl,
                                               const float* __restrict__ Wr,
                                               int n) {
    extern __shared__ unsigned smem[];
    unsigned* sW = smem;                 // 64 word-rows x SWS
    unsigned* sA = smem + 64 * SWS;      // 128 rows x SAS

    int tid = threadIdx.x;
    for (int i = tid; i < 64 * 128; i += 256) {
        int k2 = i >> 7, nn = i & 127;
        const float* W = (nn < 64) ? Wl : Wr;
        int cc = nn & 63;
        sW[k2 * SWS + nn] = pack_bf2(W[(2 * k2) * 64 + cc], W[(2 * k2 + 1) * 64 + cc]);
    }

    int node0 = blockIdx.x * 128;
    const uint2* src = (const uint2*)g_hb;
    for (int i = tid; i < 128 * 32; i += 256) {
        int r = i >> 5, c2 = i & 31;
        int node = node0 + r;
        uint2 v = make_uint2(0u, 0u);
        if (node < n) v = src[(size_t)node * 32 + c2];
        sA[r * SAS + c2 * 2]     = v.x;
        sA[r * SAS + c2 * 2 + 1] = v.y;
    }
    __syncthreads();

    int wid = tid >> 5, lane = tid & 31;
    int gid = lane >> 2, tig = lane & 3;
    int wm = wid >> 2, wn = wid & 3;

    float acc[4][4][4];
#pragma unroll
    for (int mi = 0; mi < 4; mi++)
#pragma unroll
        for (int ni = 0; ni < 4; ni++)
#pragma unroll
            for (int r = 0; r < 4; r++) acc[mi][ni][r] = 0.f;

#pragma unroll
    for (int s = 0; s < 8; s++) {
        int kw = s * 8;
        unsigned afr[4][4];
#pragma unroll
        for (int mi = 0; mi < 4; mi++) {
            int m = wm * 64 + mi * 16;
            afr[mi][0] = sA[(m + gid) * SAS + kw + tig];
            afr[mi][1] = sA[(m + gid + 8) * SAS + kw + tig];
            afr[mi][2] = sA[(m + gid) * SAS + kw + 4 + tig];
            afr[mi][3] = sA[(m + gid + 8) * SAS + kw + 4 + tig];
        }
        unsigned bfr[4][2];
#pragma unroll
        for (int ni = 0; ni < 4; ni++) {
            int nc = wn * 32 + ni * 8;
            bfr[ni][0] = sW[(kw + tig) * SWS + nc + gid];
            bfr[ni][1] = sW[(kw + 4 + tig) * SWS + nc + gid];
        }
#pragma unroll
        for (int mi = 0; mi < 4; mi++)
#pragma unroll
            for (int ni = 0; ni < 4; ni++)
                mma_bf16(acc[mi][ni], afr[mi], bfr[ni]);
    }

#pragma unroll
    for (int mi = 0; mi < 4; mi++) {
#pragma unroll
        for (int ni = 0; ni < 4; ni++) {
            int m = node0 + wm * 64 + mi * 16;
            int col = wn * 32 + ni * 8 + 2 * tig;
            int r0 = m + gid, r1 = m + gid + 8;
            if (col < 64) {
                int wrd = col >> 1;
                if (r0 < n) g_ub[(size_t)r0 * 32 + wrd] = pack_bf2(acc[mi][ni][0], acc[mi][ni][1]);
                if (r1 < n) g_ub[(size_t)r1 * 32 + wrd] = pack_bf2(acc[mi][ni][2], acc[mi][ni][3]);
            } else {
                int cc = col - 64;
                if (r0 < n) {
                    g_ur[(size_t)r0 * 64 + cc]     = acc[mi][ni][0];
                    g_ur[(size_t)r0 * 64 + cc + 1] = acc[mi][ni][1];
                }
                if (r1 < n) {
                    g_ur[(size_t)r1 * 64 + cc]     = acc[mi][ni][2];
                    g_ur[(size_t)r1 * 64 + cc + 1] = acc[mi][ni][3];
                }
            }
        }
    }
}

// -------- fused aggregation-2 + NLL loss + final write (last block) --------
__global__ void __launch_bounds__(256) k_aggr_loss(const float* __restrict__ b2,
                                                   const int* __restrict__ y,
                                                   const unsigned int* __restrict__ mask,
                                                   int n, float* __restrict__ out) {
    __shared__ float s_n[8], s_m[8];
    int warp = threadIdx.x >> 5, lane = threadIdx.x & 31;
    int w = blockIdx.x * 8 + warp;
    float nll = 0.f, mm = 0.f;
    if (w < n) {
        int start = g_offsets[w];
        int cnt   = g_counts[w];
        float2 acc = make_float2(0.f, 0.f);
        for (int i = 0; i < cnt; i++) {
            int s = g_src_sorted[start + i];
            float2 f = unpack_bf2(g_ub[(size_t)s * 32 + lane]);
            acc.x += f.x; acc.y += f.y;
        }
        float inv = 1.0f / fmaxf((float)cnt, 1.0f);
        float2 r  = ((const float2*)(g_ur + (size_t)w * 64))[lane];
        float2 bb = ((const float2*)b2)[lane];
        float l0 = acc.x * inv + r.x + bb.x;
        float l1 = acc.y * inv + r.y + bb.y;
        float mx = fmaxf(l0, l1);
        for (int o = 16; o > 0; o >>= 1) mx = fmaxf(mx, __shfl_xor_sync(0xffffffffu, mx, o));
        float s = expf(l0 - mx) + expf(l1 - mx);
        for (int o = 16; o > 0; o >>= 1) s += __shfl_xor_sync(0xffffffffu, s, o);
        float lse = mx + logf(s);
        int yy = y[w];
        float pick = (yy & 1) ? l1 : l0;
        float ly = __shfl_sync(0xffffffffu, pick, yy >> 1);
        mm = (mask[w] != 0u) ? 1.f : 0.f;
        nll = (lse - ly) * mm;
    }
    if (lane == 0) { s_n[warp] = nll; s_m[warp] = mm; }
    __syncthreads();
    if (warp == 0 && lane < 8) {
        float a = s_n[lane], b = s_m[lane];
        for (int o = 4; o > 0; o >>= 1) {
            a += __shfl_xor_sync(0xffu, a, o);
            b += __shfl_xor_sync(0xffu, b, o);
        }
        if (lane == 0) {
            atomicAdd((float*)&g_zeroed[0], a);
            atomicAdd((float*)&g_zeroed[1], b);
            __threadfence();
            int done = atomicAdd((int*)&g_zeroed[3], 1);
            if (done == gridDim.x - 1) {
                volatile float* acc = (volatile float*)g_zeroed;
                out[0] = acc[0] / fmaxf(acc[1], 1.0f);
            }
        }
    }
}

// -------- host launch: fork x-conversion onto a side stream, parallel to CSR build --------
extern "C" void kernel_launch(void* const* d_in, const int* in_sizes, int n_in,
                              void* d_out, int out_size) {
    const float* x    = (const float*)d_in[0];
    const int*   esrc = (const int*)d_in[1];
    const int*   edst = (const int*)d_in[2];
    const int*   y    = (const int*)d_in[3];
    const unsigned int* mask = (const unsigned int*)d_in[4];
    const float* W1l = (const float*)d_in[5];
    const float* b1  = (const float*)d_in[6];
    const float* W1r = (const float*)d_in[7];
    const float* W2l = (const float*)d_in[8];
    const float* b2  = (const float*)d_in[9];
    const float* W2r = (const float*)d_in[10];

    int n = in_sizes[3];   // y: [N]
    int e = in_sizes[1];   // edge_src: [E]

    const int smem1 = (128 * SWS + 128 * SAS) * 4;  // 104,448 B
    const int smem2 = (64 * SWS + 128 * SAS) * 4;   //  69,632 B
    cudaFuncSetAttribute(k_gemm1, cudaFuncAttributeMaxDynamicSharedMemorySize, smem1);
    cudaFuncSetAttribute(k_gemm2, cudaFuncAttributeMaxDynamicSharedMemorySize, smem2);

    static cudaStream_t s2 = nullptr;
    static cudaEvent_t ev_fork = nullptr, ev_join = nullptr;
    if (s2 == nullptr) {
        cudaStreamCreateWithFlags(&s2, cudaStreamNonBlocking);
        cudaEventCreateWithFlags(&ev_fork, cudaEventDisableTiming);
        cudaEventCreateWithFlags(&ev_join, cudaEventDisableTiming);
    }

    void *pcounts, *pzero;
    cudaGetSymbolAddress(&pcounts, g_counts);
    cudaGetSymbolAddress(&pzero, g_zeroed);

    // fork: x conversion on side stream, concurrent with CSR build
    cudaEventRecord(ev_fork, 0);
    cudaStreamWaitEvent(s2, ev_fork, 0);
    k_x2bf<<<(n * 32 + 255) / 256, 256, 0, s2>>>((const float4*)x, n * 32);
    cudaEventRecord(ev_join, s2);

    // main branch: CSR build
    cudaMemsetAsync(pcounts, 0, (size_t)n * sizeof(int), 0);
    cudaMemsetAsync(pzero, 0, 16, 0);
    k_hist<<<(e + 255) / 256, 256>>>(edst, e);
    k_offsets<<<(n + 255) / 256, 256>>>(n);
    k_scatter<<<(e + 255) / 256, 256>>>(esrc, edst, e);

    // join: aggregation needs both CSR and g_x8
    cudaStreamWaitEvent(0, ev_join, 0);

    k_aggr_bf<<<(n + 7) / 8, 256>>>(n);
    k_gemm1<<<(n + 127) / 128, 256, smem1>>>(W1l, W1r, b1, n);
    k_gemm2<<<(n + 127) / 128, 256, smem2>>>(W2l, W2r, n);
    k_aggr_loss<<<(n + 7) / 8, 256>>>(b2, y, mask, n, (float*)d_out);
}

// round 16
// speedup vs baseline: 1.0469x; 1.0469x over previous
#include <cuda_runtime.h>
#include <cuda_bf16.h>
#include <cuda_fp8.h>

#define MAXN 65536
#define MAXE 1048576
#define C 64

// -------- scratch (static device globals; no allocation) --------
__device__ __align__(16) unsigned g_xb [(size_t)MAXN * 64];  // x, bf16 packed pairs (GEMM input)
__device__ __align__(16) unsigned g_x8 [(size_t)MAXN * 32];  // x, fp8 e4m3 x4 (aggr-1 gather)
__device__ __align__(16) unsigned g_a1b[(size_t)MAXN * 64];  // aggr(x), bf16
__device__ __align__(16) unsigned g_hb [(size_t)MAXN * 64];  // h, bf16
__device__ __align__(16) unsigned short g_u8[(size_t)MAXN * 32]; // u_l, fp8x2 (64 wide)
__device__ __align__(16) float    g_ur [(size_t)MAXN * C];   // u_r, fp32
__device__ __align__(16) unsigned g_w1p[128 * 128];          // W1 pre-packed bf16x2 (sW layout)
__device__ __align__(16) unsigned g_w2p[64 * 128];           // W2 pre-packed bf16x2 (sW layout)
__device__ int g_counts[MAXN];
__device__ int g_offsets[MAXN];
__device__ int g_rank[MAXE];          // within-bucket rank of each edge
__device__ int g_src_sorted[MAXE];
__device__ __align__(16) unsigned g_zeroed[4];   // [0..1]=acc(float), [2]=total, [3]=done

__device__ __forceinline__ unsigned pack_bf2(float a, float b) {
    __nv_bfloat162 p = __floats2bfloat162_rn(a, b);
    return *reinterpret_cast<unsigned*>(&p);
}
__device__ __forceinline__ float2 unpack_bf2(unsigned w) {
    return __bfloat1622float2(*reinterpret_cast<__nv_bfloat162*>(&w));
}
__device__ __forceinline__ float2 fp8x2_to_f2(unsigned short v) {
    __half2_raw hr = __nv_cvt_fp8x2_to_halfraw2((__nv_fp8x2_storage_t)v, __NV_E4M3);
    return __half22float2(*reinterpret_cast<__half2*>(&hr));
}

__device__ __forceinline__ void mma_bf16(float c[4], const unsigned a[4], const unsigned b[2]) {
    asm volatile(
        "mma.sync.aligned.m16n8k16.row.col.f32.bf16.bf16.f32 "
        "{%0,%1,%2,%3}, {%4,%5,%6,%7}, {%8,%9}, {%0,%1,%2,%3};"
        : "+f"(c[0]), "+f"(c[1]), "+f"(c[2]), "+f"(c[3])
        : "r"(a[0]), "r"(a[1]), "r"(a[2]), "r"(a[3]), "r"(b[0]), "r"(b[1]));
}

// -------- x -> bf16 + fp8, AND one-time bf16 weight pre-pack (first blocks) --------
__global__ void k_x2bf(const float4* __restrict__ x, int nwords4,
                       const float* __restrict__ W1l, const float* __restrict__ W1r,
                       const float* __restrict__ W2l, const float* __restrict__ W2r) {
    int i = blockIdx.x * blockDim.x + threadIdx.x;
    if (i < 128 * 128) {           // W1 pack: word-row k2 packs k=2*k2,2*k2+1
        int k2 = i >> 7, nn = i & 127;
        const float* W = (k2 < 64) ? W1l : W1r;
        int kk = (k2 & 63) * 2;
        g_w1p[i] = pack_bf2(W[kk * 128 + nn], W[(kk + 1) * 128 + nn]);
    }
    if (i < 64 * 128) {            // W2 pack
        int k2 = i >> 7, nn = i & 127;
        const float* W = (nn < 64) ? W2l : W2r;
        int cc = nn & 63;
        g_w2p[i] = pack_bf2(W[(2 * k2) * 64 + cc], W[(2 * k2 + 1) * 64 + cc]);
    }
    if (i < nwords4) {
        float4 v = x[i];
        ((uint2*)g_xb)[i] = make_uint2(pack_bf2(v.x, v.y), pack_bf2(v.z, v.w));
        unsigned lo = (unsigned)__nv_cvt_float2_to_fp8x2(make_float2(v.x, v.y),
                                                         __NV_SATFINITE, __NV_E4M3);
        unsigned hi = (unsigned)__nv_cvt_float2_to_fp8x2(make_float2(v.z, v.w),
                                                         __NV_SATFINITE, __NV_E4M3);
        g_x8[i] = lo | (hi << 16);
    }
}

// -------- histogram; the atomic's return value IS the edge's bucket rank --------
__global__ void k_hist(const int* __restrict__ dst, int e) {
    int i = blockIdx.x * blockDim.x + threadIdx.x;
    if (i < e) {
        int d = dst[i];
        g_rank[i] = atomicAdd(&g_counts[d], 1);
    }
}

// -------- offsets via warp scan + one atomic per warp --------
__global__ void k_offsets(int n) {
    int i = blockIdx.x * blockDim.x + threadIdx.x;
    int lane = threadIdx.x & 31;
    int c = (i < n) ? g_counts[i] : 0;
    int s = c;
#pragma unroll
    for (int o = 1; o < 32; o <<= 1) {
        int t = __shfl_up_sync(0xffffffffu, s, o);
        if (lane >= o) s += t;
    }
    int total = __shfl_sync(0xffffffffu, s, 31);
    int base = 0;
    if (lane == 31) base = atomicAdd((int*)&g_zeroed[2], total);
    base = __shfl_sync(0xffffffffu, base, 31);
    if (i < n) g_offsets[i] = base + s - c;
}

// -------- atomic-free scatter: position = offset[dst] + rank --------
__global__ void k_scatter(const int* __restrict__ src, const int* __restrict__ dst, int e) {
    int i = blockIdx.x * blockDim.x + threadIdx.x;
    if (i < e) {
        int d = dst[i];
        g_src_sorted[g_offsets[d] + g_rank[i]] = src[i];
    }
}

// -------- aggregation 1: mean of fp8 x rows -> bf16 (warp per node) --------
__global__ void __launch_bounds__(256) k_aggr_bf(int n) {
    int w    = (blockIdx.x * blockDim.x + threadIdx.x) >> 5;
    int lane = threadIdx.x & 31;
    if (w >= n) return;
    int start = g_offsets[w];
    int cnt   = g_counts[w];
    float4 acc = make_float4(0.f, 0.f, 0.f, 0.f);
    for (int i = 0; i < cnt; i++) {
        int s = g_src_sorted[start + i];
        unsigned v = g_x8[(size_t)s * 32 + lane];
        float2 f0 = fp8x2_to_f2((unsigned short)(v & 0xffffu));
        float2 f1 = fp8x2_to_f2((unsigned short)(v >> 16));
        acc.x += f0.x; acc.y += f0.y; acc.z += f1.x; acc.w += f1.y;
    }
    float inv = 1.0f / fmaxf((float)cnt, 1.0f);
    ((uint2*)(g_a1b + (size_t)w * 64))[lane] =
        make_uint2(pack_bf2(acc.x * inv, acc.y * inv), pack_bf2(acc.z * inv, acc.w * inv));
}

// ======== bf16 tensor-core GEMM, layer 1 ========
#define SWS 136   // sW word stride
#define SAS 68    // sA word stride

__global__ void __launch_bounds__(256) k_gemm1(const float* __restrict__ bias, int n) {
    extern __shared__ unsigned smem[];
    unsigned* sW = smem;                  // 128 word-rows x SWS
    unsigned* sA = smem + 128 * SWS;      // 128 rows x SAS

    int tid = threadIdx.x;
    // linear uint4 copy of pre-packed bf16 weights into strided smem layout
    for (int i = tid; i < 4096; i += 256) {
        int k2 = i >> 5, c4 = i & 31;
        ((uint4*)(sW + k2 * SWS))[c4] = ((const uint4*)g_w1p)[i];
    }

    int node0 = blockIdx.x * 128;
    int wid = tid >> 5, lane = tid & 31;
    int gid = lane >> 2, tig = lane & 3;
    int wm = wid >> 2, wn = wid & 3;

    float acc[4][4][4];
#pragma unroll
    for (int mi = 0; mi < 4; mi++)
#pragma unroll
        for (int ni = 0; ni < 4; ni++)
#pragma unroll
            for (int r = 0; r < 4; r++) acc[mi][ni][r] = 0.f;

#pragma unroll
    for (int phase = 0; phase < 2; phase++) {
        const uint2* src = (const uint2*)(phase == 0 ? g_a1b : g_xb);
        __syncthreads();
        for (int i = tid; i < 128 * 32; i += 256) {
            int r = i >> 5, c2 = i & 31;
            int node = node0 + r;
            uint2 v = make_uint2(0u, 0u);
            if (node < n) v = src[(size_t)node * 32 + c2];
            sA[r * SAS + c2 * 2]     = v.x;
            sA[r * SAS + c2 * 2 + 1] = v.y;
        }
        __syncthreads();

        int kw0 = phase * 64;
#pragma unroll
        for (int s = 0; s < 8; s++) {
            int kw = s * 8;
            unsigned afr[4][4];
#pragma unroll
            for (int mi = 0; mi < 4; mi++) {
                int m = wm * 64 + mi * 16;
                afr[mi][0] = sA[(m + gid) * SAS + kw + tig];
                afr[mi][1] = sA[(m + gid + 8) * SAS + kw + tig];
                afr[mi][2] = sA[(m + gid) * SAS + kw + 4 + tig];
                afr[mi][3] = sA[(m + gid + 8) * SAS + kw + 4 + tig];
            }
            unsigned bfr[4][2];
#pragma unroll
            for (int ni = 0; ni < 4; ni++) {
                int nc = wn * 32 + ni * 8;
                bfr[ni][0] = sW[(kw0 + kw + tig) * SWS + nc + gid];
                bfr[ni][1] = sW[(kw0 + kw + 4 + tig) * SWS + nc + gid];
            }
#pragma unroll
            for (int mi = 0; mi < 4; mi++)
#pragma unroll
                for (int ni = 0; ni < 4; ni++)
                    mma_bf16(acc[mi][ni], afr[mi], bfr[ni]);
        }
    }

    // epilogue: bias + relu -> bf16 packed h
#pragma unroll
    for (int mi = 0; mi < 4; mi++) {
#pragma unroll
        for (int ni = 0; ni < 4; ni++) {
            int m = node0 + wm * 64 + mi * 16;
            int col = wn * 32 + ni * 8 + 2 * tig;
            float bv0 = bias[col], bv1 = bias[col + 1];
            int r0 = m + gid, r1 = m + gid + 8;
            int wrd = col >> 1;
            if (r0 < n)
                g_hb[(size_t)r0 * 64 + wrd] = pack_bf2(fmaxf(acc[mi][ni][0] + bv0, 0.f),
                                                       fmaxf(acc[mi][ni][1] + bv1, 0.f));
            if (r1 < n)
                g_hb[(size_t)r1 * 64 + wrd] = pack_bf2(fmaxf(acc[mi][ni][2] + bv0, 0.f),
                                                       fmaxf(acc[mi][ni][3] + bv1, 0.f));
        }
    }
}

// ======== bf16 GEMM, layer 2: u = h @ [W2l | W2r] ========
// u_l (cols 0..63) -> fp8x2 g_u8;  u_r (cols 64..127) -> fp32 g_ur
__global__ void __launch_bounds__(256) k_gemm2(int n) {
    extern __shared__ unsigned smem[];
    unsigned* sW = smem;                 // 64 word-rows x SWS
    unsigned* sA = smem + 64 * SWS;      // 128 rows x SAS

    int tid = threadIdx.x;
    for (int i = tid; i < 2048; i += 256) {
        int k2 = i >> 5, c4 = i & 31;
        ((uint4*)(sW + k2 * SWS))[c4] = ((const uint4*)g_w2p)[i];
    }

    int node0 = blockIdx.x * 128;
    const uint2* src = (const uint2*)g_hb;
    for (int i = tid; i < 128 * 32; i += 256) {
        int r = i >> 5, c2 = i & 31;
        int node = node0 + r;
        uint2 v = make_uint2(0u, 0u);
        if (node < n) v = src[(size_t)node * 32 + c2];
        sA[r * SAS + c2 * 2]     = v.x;
        sA[r * SAS + c2 * 2 + 1] = v.y;
    }
    __syncthreads();

    int wid = tid >> 5, lane = tid & 31;
    int gid = lane >> 2, tig = lane & 3;
    int wm = wid >> 2, wn = wid & 3;

    float acc[4][4][4];
#pragma unroll
    for (int mi = 0; mi < 4; mi++)
#pragma unroll
        for (int ni = 0; ni < 4; ni++)
#pragma unroll
            for (int r = 0; r < 4; r++) acc[mi][ni][r] = 0.f;

#pragma unroll
    for (int s = 0; s < 8; s++) {
        int kw = s * 8;
        unsigned afr[4][4];
#pragma unroll
        for (int mi = 0; mi < 4; mi++) {
            int m = wm * 64 + mi * 16;
            afr[mi][0] = sA[(m + gid) * SAS + kw + tig];
            afr[mi][1] = sA[(m + gid + 8) * SAS + kw + tig];
            afr[mi][2] = sA[(m + gid) * SAS + kw + 4 + tig];
            afr[mi][3] = sA[(m + gid + 8) * SAS + kw + 4 + tig];
        }
        unsigned bfr[4][2];
#pragma unroll
        for (int ni = 0; ni < 4; ni++) {
            int nc = wn * 32 + ni * 8;
            bfr[ni][0] = sW[(kw + tig) * SWS + nc + gid];
            bfr[ni][1] = sW[(kw + 4 + tig) * SWS + nc + gid];
        }
#pragma unroll
        for (int mi = 0; mi < 4; mi++)
#pragma unroll
            for (int ni = 0; ni < 4; ni++)
                mma_bf16(acc[mi][ni], afr[mi], bfr[ni]);
    }

#pragma unroll
    for (int mi = 0; mi < 4; mi++) {
#pragma unroll
        for (int ni = 0; ni < 4; ni++) {
            int m = node0 + wm * 64 + mi * 16;
            int col = wn * 32 + ni * 8 + 2 * tig;
            int r0 = m + gid, r1 = m + gid + 8;
            if (col < 64) {
                int wrd = col >> 1;
                if (r0 < n)
                    g_u8[(size_t)r0 * 32 + wrd] = (unsigned short)__nv_cvt_float2_to_fp8x2(
                        make_float2(acc[mi][ni][0], acc[mi][ni][1]), __NV_SATFINITE, __NV_E4M3);
                if (r1 < n)
                    g_u8[(size_t)r1 * 32 + wrd] = (unsigned short)__nv_cvt_float2_to_fp8x2(
                        make_float2(acc[mi][ni][2], acc[mi][ni][3]), __NV_SATFINITE, __NV_E4M3);
            } else {
                int cc = col - 64;
                if (r0 < n) {
                    g_ur[(size_t)r0 * 64 + cc]     = acc[mi][ni][0];
                    g_ur[(size_t)r0 * 64 + cc + 1] = acc[mi][ni][1];
                }
                if (r1 < n) {
                    g_ur[(size_t)r1 * 64 + cc]     = acc[mi][ni][2];
                    g_ur[(size_t)r1 * 64 + cc + 1] = acc[mi][ni][3];
                }
            }
        }
    }
}

// -------- fused aggregation-2 (fp8 u_l) + NLL loss + final write (last block) --------
__global__ void __launch_bounds__(256) k_aggr_loss(const float* __restrict__ b2,
                                                   const int* __restrict__ y,
                                                   const unsigned int* __restrict__ mask,
                                                   int n, float* __restrict__ out) {
    __shared__ float s_n[8], s_m[8];
    int warp = threadIdx.x >> 5, lane = threadIdx.x & 31;
    int w = blockIdx.x * 8 + warp;
    float nll = 0.f, mm = 0.f;
    if (w < n) {
        int start = g_offsets[w];
        int cnt   = g_counts[w];
        float2 acc = make_float2(0.f, 0.f);
        for (int i = 0; i < cnt; i++) {
            int s = g_src_sorted[start + i];
            float2 f = fp8x2_to_f2(g_u8[(size_t)s * 32 + lane]);
            acc.x += f.x; acc.y += f.y;
        }
        float inv = 1.0f / fmaxf((float)cnt, 1.0f);
        float2 r  = ((const float2*)(g_ur + (size_t)w * 64))[lane];
        float2 bb = ((const float2*)b2)[lane];
        float l0 = acc.x * inv + r.x + bb.x;
        float l1 = acc.y * inv + r.y + bb.y;
        float mx = fmaxf(l0, l1);
        for (int o = 16; o > 0; o >>= 1) mx = fmaxf(mx, __shfl_xor_sync(0xffffffffu, mx, o));
        float s = expf(l0 - mx) + expf(l1 - mx);
        for (int o = 16; o > 0; o >>= 1) s += __shfl_xor_sync(0xffffffffu, s, o);
        float lse = mx + logf(s);
        int yy = y[w];
        float pick = (yy & 1) ? l1 : l0;
        float ly = __shfl_sync(0xffffffffu, pick, yy >> 1);
        mm = (mask[w] != 0u) ? 1.f : 0.f;
        nll = (lse - ly) * mm;
    }
    if (lane == 0) { s_n[warp] = nll; s_m[warp] = mm; }
    __syncthreads();
    if (warp == 0 && lane < 8) {
        float a = s_n[lane], b = s_m[lane];
        for (int o = 4; o > 0; o >>= 1) {
            a += __shfl_xor_sync(0xffu, a, o);
            b += __shfl_xor_sync(0xffu, b, o);
        }
        if (lane == 0) {
            atomicAdd((float*)&g_zeroed[0], a);
            atomicAdd((float*)&g_zeroed[1], b);
            __threadfence();
            int done = atomicAdd((int*)&g_zeroed[3], 1);
            if (done == gridDim.x - 1) {
                volatile float* acc = (volatile float*)g_zeroed;
                out[0] = acc[0] / fmaxf(acc[1], 1.0f);
            }
        }
    }
}

// -------- host launch (single stream, R10-proven ordering) --------
extern "C" void kernel_launch(void* const* d_in, const int* in_sizes, int n_in,
                              void* d_out, int out_size) {
    const float* x    = (const float*)d_in[0];
    const int*   esrc = (const int*)d_in[1];
    const int*   edst = (const int*)d_in[2];
    const int*   y    = (const int*)d_in[3];
    const unsigned int* mask = (const unsigned int*)d_in[4];
    const float* W1l = (const float*)d_in[5];
    const float* b1  = (const float*)d_in[6];
    const float* W1r = (const float*)d_in[7];
    const float* W2l = (const float*)d_in[8];
    const float* b2  = (const float*)d_in[9];
    const float* W2r = (const float*)d_in[10];

    int n = in_sizes[3];   // y: [N]
    int e = in_sizes[1];   // edge_src: [E]

    const int smem1 = (128 * SWS + 128 * SAS) * 4;  // 104,448 B
    const int smem2 = (64 * SWS + 128 * SAS) * 4;   //  69,632 B
    cudaFuncSetAttribute(k_gemm1, cudaFuncAttributeMaxDynamicSharedMemorySize, smem1);
    cudaFuncSetAttribute(k_gemm2, cudaFuncAttributeMaxDynamicSharedMemorySize, smem2);

    void *pcounts, *pzero;
    cudaGetSymbolAddress(&pcounts, g_counts);
    cudaGetSymbolAddress(&pzero, g_zeroed);
    cudaMemsetAsync(pcounts, 0, (size_t)n * sizeof(int), 0);
    cudaMemsetAsync(pzero, 0, 16, 0);

    k_x2bf<<<(n * 32 + 255) / 256, 256>>>((const float4*)x, n * 32, W1l, W1r, W2l, W2r);
    k_hist<<<(e + 255) / 256, 256>>>(edst, e);
    k_offsets<<<(n + 255) / 256, 256>>>(n);
    k_scatter<<<(e + 255) / 256, 256>>>(esrc, edst, e);

    k_aggr_bf<<<(n + 7) / 8, 256>>>(n);
    k_gemm1<<<(n + 127) / 128, 256, smem1>>>(b1, n);
    k_gemm2<<<(n + 127) / 128, 256, smem2>>>(n);
    k_aggr_loss<<<(n + 7) / 8, 256>>>(b2, y, mask, n, (float*)d_out);
}

// round 17
// speedup vs baseline: 1.0733x; 1.0252x over previous
#include <cuda_runtime.h>
#include <cuda_bf16.h>
#include <cuda_fp8.h>

#define MAXN 65536
#define MAXE 1048576
#define C 64

// -------- scratch (static device globals; no allocation) --------
__device__ __align__(16) unsigned g_xb [(size_t)MAXN * 64];  // x, bf16 packed pairs (GEMM input)
__device__ __align__(16) unsigned g_x8 [(size_t)MAXN * 32];  // x, fp8 e4m3 x4 (aggr-1 gather)
__device__ __align__(16) unsigned g_a1b[(size_t)MAXN * 64];  // aggr(x), bf16
__device__ __align__(16) unsigned g_hb [(size_t)MAXN * 64];  // h, bf16
__device__ __align__(16) unsigned short g_u8[(size_t)MAXN * 32]; // u_l, fp8x2 (64 wide)
__device__ __align__(16) float    g_ur [(size_t)MAXN * C];   // u_r, fp32
__device__ __align__(16) unsigned g_w1p[128 * 128];          // W1 pre-packed bf16x2 (sW layout)
__device__ __align__(16) unsigned g_w2p[64 * 128];           // W2 pre-packed bf16x2 (sW layout)
__device__ int g_counts[MAXN];
__device__ int g_offsets[MAXN];
__device__ int g_rank[MAXE];          // within-bucket rank of each edge
__device__ int g_src_sorted[MAXE];
__device__ __align__(16) unsigned g_zeroed[4];   // [0..1]=acc(float), [2]=total, [3]=done

__device__ __forceinline__ unsigned pack_bf2(float a, float b) {
    __nv_bfloat162 p = __floats2bfloat162_rn(a, b);
    return *reinterpret_cast<unsigned*>(&p);
}
__device__ __forceinline__ float2 unpack_bf2(unsigned w) {
    return __bfloat1622float2(*reinterpret_cast<__nv_bfloat162*>(&w));
}
__device__ __forceinline__ float2 fp8x2_to_f2(unsigned short v) {
    __half2_raw hr = __nv_cvt_fp8x2_to_halfraw2((__nv_fp8x2_storage_t)v, __NV_E4M3);
    return __half22float2(*reinterpret_cast<__half2*>(&hr));
}

__device__ __forceinline__ void mma_bf16(float c[4], const unsigned a[4], const unsigned b[2]) {
    asm volatile(
        "mma.sync.aligned.m16n8k16.row.col.f32.bf16.bf16.f32 "
        "{%0,%1,%2,%3}, {%4,%5,%6,%7}, {%8,%9}, {%0,%1,%2,%3};"
        : "+f"(c[0]), "+f"(c[1]), "+f"(c[2]), "+f"(c[3])
        : "r"(a[0]), "r"(a[1]), "r"(a[2]), "r"(a[3]), "r"(b[0]), "r"(b[1]));
}

// -------- fused: x -> bf16/fp8 conversion + edge histogram + weight pre-pack --------
// g_counts is zeroed by the preceding memset; g_zeroed is zeroed here (consumed
// two launches later by k_offsets / k_aggr_loss).
__global__ void k_xhist(const float4* __restrict__ x, int nwords4,
                        const int* __restrict__ dst, int e,
                        const float* __restrict__ W1l, const float* __restrict__ W1r,
                        const float* __restrict__ W2l, const float* __restrict__ W2r) {
    int i = blockIdx.x * blockDim.x + threadIdx.x;
    if (i < 4) g_zeroed[i] = 0u;
    if (i < 128 * 128) {           // W1 pack: word-row k2 packs k=2*k2,2*k2+1
        int k2 = i >> 7, nn = i & 127;
        const float* W = (k2 < 64) ? W1l : W1r;
        int kk = (k2 & 63) * 2;
        g_w1p[i] = pack_bf2(W[kk * 128 + nn], W[(kk + 1) * 128 + nn]);
    }
    if (i < 64 * 128) {            // W2 pack
        int k2 = i >> 7, nn = i & 127;
        const float* W = (nn < 64) ? W2l : W2r;
        int cc = nn & 63;
        g_w2p[i] = pack_bf2(W[(2 * k2) * 64 + cc], W[(2 * k2 + 1) * 64 + cc]);
    }
    if (i < e) {                   // histogram; atomic return value IS the rank
        g_rank[i] = atomicAdd(&g_counts[dst[i]], 1);
    }
    if (i < nwords4) {
        float4 v = x[i];
        ((uint2*)g_xb)[i] = make_uint2(pack_bf2(v.x, v.y), pack_bf2(v.z, v.w));
        unsigned lo = (unsigned)__nv_cvt_float2_to_fp8x2(make_float2(v.x, v.y),
                                                         __NV_SATFINITE, __NV_E4M3);
        unsigned hi = (unsigned)__nv_cvt_float2_to_fp8x2(make_float2(v.z, v.w),
                                                         __NV_SATFINITE, __NV_E4M3);
        g_x8[i] = lo | (hi << 16);
    }
}

// -------- offsets via warp scan + one atomic per warp --------
__global__ void k_offsets(int n) {
    int i = blockIdx.x * blockDim.x + threadIdx.x;
    int lane = threadIdx.x & 31;
    int c = (i < n) ? g_counts[i] : 0;
    int s = c;
#pragma unroll
    for (int o = 1; o < 32; o <<= 1) {
        int t = __shfl_up_sync(0xffffffffu, s, o);
        if (lane >= o) s += t;
    }
    int total = __shfl_sync(0xffffffffu, s, 31);
    int base = 0;
    if (lane == 31) base = atomicAdd((int*)&g_zeroed[2], total);
    base = __shfl_sync(0xffffffffu, base, 31);
    if (i < n) g_offsets[i] = base + s - c;
}

// -------- atomic-free scatter: position = offset[dst] + rank --------
__global__ void k_scatter(const int* __restrict__ src, const int* __restrict__ dst, int e) {
    int i = blockIdx.x * blockDim.x + threadIdx.x;
    if (i < e) {
        int d = dst[i];
        g_src_sorted[g_offsets[d] + g_rank[i]] = src[i];
    }
}

// -------- aggregation 1: mean of fp8 x rows -> bf16 (warp per node) --------
__global__ void __launch_bounds__(256) k_aggr_bf(int n) {
    int w    = (blockIdx.x * blockDim.x + threadIdx.x) >> 5;
    int lane = threadIdx.x & 31;
    if (w >= n) return;
    int start = g_offsets[w];
    int cnt   = g_counts[w];
    float4 acc = make_float4(0.f, 0.f, 0.f, 0.f);
    for (int i = 0; i < cnt; i++) {
        int s = g_src_sorted[start + i];
        unsigned v = g_x8[(size_t)s * 32 + lane];
        float2 f0 = fp8x2_to_f2((unsigned short)(v & 0xffffu));
        float2 f1 = fp8x2_to_f2((unsigned short)(v >> 16));
        acc.x += f0.x; acc.y += f0.y; acc.z += f1.x; acc.w += f1.y;
    }
    float inv = 1.0f / fmaxf((float)cnt, 1.0f);
    ((uint2*)(g_a1b + (size_t)w * 64))[lane] =
        make_uint2(pack_bf2(acc.x * inv, acc.y * inv), pack_bf2(acc.z * inv, acc.w * inv));
}

// ======== bf16 tensor-core GEMM, layer 1 ========
#define SWS 136   // sW word stride
#define SAS 68    // sA word stride

__global__ void __launch_bounds__(256) k_gemm1(const float* __restrict__ bias, int n) {
    extern __shared__ unsigned smem[];
    unsigned* sW = smem;                  // 128 word-rows x SWS
    unsigned* sA = smem + 128 * SWS;      // 128 rows x SAS

    int tid = threadIdx.x;
    for (int i = tid; i < 4096; i += 256) {
        int k2 = i >> 5, c4 = i & 31;
        ((uint4*)(sW + k2 * SWS))[c4] = ((const uint4*)g_w1p)[i];
    }

    int node0 = blockIdx.x * 128;
    int wid = tid >> 5, lane = tid & 31;
    int gid = lane >> 2, tig = lane & 3;
    int wm = wid >> 2, wn = wid & 3;

    float acc[4][4][4];
#pragma unroll
    for (int mi = 0; mi < 4; mi++)
#pragma unroll
        for (int ni = 0; ni < 4; ni++)
#pragma unroll
            for (int r = 0; r < 4; r++) acc[mi][ni][r] = 0.f;

#pragma unroll
    for (int phase = 0; phase < 2; phase++) {
        const uint2* src = (const uint2*)(phase == 0 ? g_a1b : g_xb);
        __syncthreads();
        for (int i = tid; i < 128 * 32; i += 256) {
            int r = i >> 5, c2 = i & 31;
            int node = node0 + r;
            uint2 v = make_uint2(0u, 0u);
            if (node < n) v = src[(size_t)node * 32 + c2];
            sA[r * SAS + c2 * 2]     = v.x;
            sA[r * SAS + c2 * 2 + 1] = v.y;
        }
        __syncthreads();

        int kw0 = phase * 64;
#pragma unroll
        for (int s = 0; s < 8; s++) {
            int kw = s * 8;
            unsigned afr[4][4];
#pragma unroll
            for (int mi = 0; mi < 4; mi++) {
                int m = wm * 64 + mi * 16;
                afr[mi][0] = sA[(m + gid) * SAS + kw + tig];
                afr[mi][1] = sA[(m + gid + 8) * SAS + kw + tig];
                afr[mi][2] = sA[(m + gid) * SAS + kw + 4 + tig];
                afr[mi][3] = sA[(m + gid + 8) * SAS + kw + 4 + tig];
            }
            unsigned bfr[4][2];
#pragma unroll
            for (int ni = 0; ni < 4; ni++) {
                int nc = wn * 32 + ni * 8;
                bfr[ni][0] = sW[(kw0 + kw + tig) * SWS + nc + gid];
                bfr[ni][1] = sW[(kw0 + kw + 4 + tig) * SWS + nc + gid];
            }
#pragma unroll
            for (int mi = 0; mi < 4; mi++)
#pragma unroll
                for (int ni = 0; ni < 4; ni++)
                    mma_bf16(acc[mi][ni], afr[mi], bfr[ni]);
        }
    }

    // epilogue: bias + relu -> bf16 packed h
#pragma unroll
    for (int mi = 0; mi < 4; mi++) {
#pragma unroll
        for (int ni = 0; ni < 4; ni++) {
            int m = node0 + wm * 64 + mi * 16;
            int col = wn * 32 + ni * 8 + 2 * tig;
            float bv0 = bias[col], bv1 = bias[col + 1];
            int r0 = m + gid, r1 = m + gid + 8;
            int wrd = col >> 1;
            if (r0 < n)
                g_hb[(size_t)r0 * 64 + wrd] = pack_bf2(fmaxf(acc[mi][ni][0] + bv0, 0.f),
                                                       fmaxf(acc[mi][ni][1] + bv1, 0.f));
            if (r1 < n)
                g_hb[(size_t)r1 * 64 + wrd] = pack_bf2(fmaxf(acc[mi][ni][2] + bv0, 0.f),
                                                       fmaxf(acc[mi][ni][3] + bv1, 0.f));
        }
    }
}

// ======== bf16 GEMM, layer 2: u = h @ [W2l | W2r] ========
// u_l (cols 0..63) -> fp8x2 g_u8;  u_r (cols 64..127) -> fp32 g_ur
__global__ void __launch_bounds__(256) k_gemm2(int n) {
    extern __shared__ unsigned smem[];
    unsigned* sW = smem;                 // 64 word-rows x SWS
    unsigned* sA = smem + 64 * SWS;      // 128 rows x SAS

    int tid = threadIdx.x;
    for (int i = tid; i < 2048; i += 256) {
        int k2 = i >> 5, c4 = i & 31;
        ((uint4*)(sW + k2 * SWS))[c4] = ((const uint4*)g_w2p)[i];
    }

    int node0 = blockIdx.x * 128;
    const uint2* src = (const uint2*)g_hb;
    for (int i = tid; i < 128 * 32; i += 256) {
        int r = i >> 5, c2 = i & 31;
        int node = node0 + r;
        uint2 v = make_uint2(0u, 0u);
        if (node < n) v = src[(size_t)node * 32 + c2];
        sA[r * SAS + c2 * 2]     = v.x;
        sA[r * SAS + c2 * 2 + 1] = v.y;
    }
    __syncthreads();

    int wid = tid >> 5, lane = tid & 31;
    int gid = lane >> 2, tig = lane & 3;
    int wm = wid >> 2, wn = wid & 3;

    float acc[4][4][4];
#pragma unroll
    for (int mi = 0; mi < 4; mi++)
#pragma unroll
        for (int ni = 0; ni < 4; ni++)
#pragma unroll
            for (int r = 0; r < 4; r++) acc[mi][ni][r] = 0.f;

#pragma unroll
    for (int s = 0; s < 8; s++) {
        int kw = s * 8;
        unsigned afr[4][4];
#pragma unroll
        for (int mi = 0; mi < 4; mi++) {
            int m = wm * 64 + mi * 16;
            afr[mi][0] = sA[(m + gid) * SAS + kw + tig];
            afr[mi][1] = sA[(m + gid + 8) * SAS + kw + tig];
            afr[mi][2] = sA[(m + gid) * SAS + kw + 4 + tig];
            afr[mi][3] = sA[(m + gid + 8) * SAS + kw + 4 + tig];
        }
        unsigned bfr[4][2];
#pragma unroll
        for (int ni = 0; ni < 4; ni++) {
            int nc = wn * 32 + ni * 8;
            bfr[ni][0] = sW[(kw + tig) * SWS + nc + gid];
            bfr[ni][1] = sW[(kw + 4 + tig) * SWS + nc + gid];
        }
#pragma unroll
        for (int mi = 0; mi < 4; mi++)
#pragma unroll
            for (int ni = 0; ni < 4; ni++)
                mma_bf16(acc[mi][ni], afr[mi], bfr[ni]);
    }

#pragma unroll
    for (int mi = 0; mi < 4; mi++) {
#pragma unroll
        for (int ni = 0; ni < 4; ni++) {
            int m = node0 + wm * 64 + mi * 16;
            int col = wn * 32 + ni * 8 + 2 * tig;
            int r0 = m + gid, r1 = m + gid + 8;
            if (col < 64) {
                int wrd = col >> 1;
                if (r0 < n)
                    g_u8[(size_t)r0 * 32 + wrd] = (unsigned short)__nv_cvt_float2_to_fp8x2(
                        make_float2(acc[mi][ni][0], acc[mi][ni][1]), __NV_SATFINITE, __NV_E4M3);
                if (r1 < n)
                    g_u8[(size_t)r1 * 32 + wrd] = (unsigned short)__nv_cvt_float2_to_fp8x2(
                        make_float2(acc[mi][ni][2], acc[mi][ni][3]), __NV_SATFINITE, __NV_E4M3);
            } else {
                int cc = col - 64;
                if (r0 < n) {
                    g_ur[(size_t)r0 * 64 + cc]     = acc[mi][ni][0];
                    g_ur[(size_t)r0 * 64 + cc + 1] = acc[mi][ni][1];
                }
                if (r1 < n) {
                    g_ur[(size_t)r1 * 64 + cc]     = acc[mi][ni][2];
                    g_ur[(size_t)r1 * 64 + cc + 1] = acc[mi][ni][3];
                }
            }
        }
    }
}

// -------- fused aggregation-2 (fp8 u_l) + NLL loss + final write (last block) --------
__global__ void __launch_bounds__(256) k_aggr_loss(const float* __restrict__ b2,
                                                   const int* __restrict__ y,
                                                   const unsigned int* __restrict__ mask,
                                                   int n, float* __restrict__ out) {
    __shared__ float s_n[8], s_m[8];
    int warp = threadIdx.x >> 5, lane = threadIdx.x & 31;
    int w = blockIdx.x * 8 + warp;
    float nll = 0.f, mm = 0.f;
    if (w < n) {
        int start = g_offsets[w];
        int cnt   = g_counts[w];
        float2 acc = make_float2(0.f, 0.f);
        for (int i = 0; i < cnt; i++) {
            int s = g_src_sorted[start + i];
            float2 f = fp8x2_to_f2(g_u8[(size_t)s * 32 + lane]);
            acc.x += f.x; acc.y += f.y;
        }
        float inv = 1.0f / fmaxf((float)cnt, 1.0f);
        float2 r  = ((const float2*)(g_ur + (size_t)w * 64))[lane];
        float2 bb = ((const float2*)b2)[lane];
        float l0 = acc.x * inv + r.x + bb.x;
        float l1 = acc.y * inv + r.y + bb.y;
        float mx = fmaxf(l0, l1);
        for (int o = 16; o > 0; o >>= 1) mx = fmaxf(mx, __shfl_xor_sync(0xffffffffu, mx, o));
        float s = expf(l0 - mx) + expf(l1 - mx);
        for (int o = 16; o > 0; o >>= 1) s += __shfl_xor_sync(0xffffffffu, s, o);
        float lse = mx + logf(s);
        int yy = y[w];
        float pick = (yy & 1) ? l1 : l0;
        float ly = __shfl_sync(0xffffffffu, pick, yy >> 1);
        mm = (mask[w] != 0u) ? 1.f : 0.f;
        nll = (lse - ly) * mm;
    }
    if (lane == 0) { s_n[warp] = nll; s_m[warp] = mm; }
    __syncthreads();
    if (warp == 0 && lane < 8) {
        float a = s_n[lane], b = s_m[lane];
        for (int o = 4; o > 0; o >>= 1) {
            a += __shfl_xor_sync(0xffu, a, o);
            b += __shfl_xor_sync(0xffu, b, o);
        }
        if (lane == 0) {
            atomicAdd((float*)&g_zeroed[0], a);
            atomicAdd((float*)&g_zeroed[1], b);
            __threadfence();
            int done = atomicAdd((int*)&g_zeroed[3], 1);
            if (done == gridDim.x - 1) {
                volatile float* acc = (volatile float*)g_zeroed;
                out[0] = acc[0] / fmaxf(acc[1], 1.0f);
            }
        }
    }
}

// -------- host launch (single stream, 8 graph nodes) --------
extern "C" void kernel_launch(void* const* d_in, const int* in_sizes, int n_in,
                              void* d_out, int out_size) {
    const float* x    = (const float*)d_in[0];
    const int*   esrc = (const int*)d_in[1];
    const int*   edst = (const int*)d_in[2];
    const int*   y    = (const int*)d_in[3];
    const unsigned int* mask = (const unsigned int*)d_in[4];
    const float* W1l = (const float*)d_in[5];
    const float* b1  = (const float*)d_in[6];
    const float* W1r = (const float*)d_in[7];
    const float* W2l = (const float*)d_in[8];
    const float* b2  = (const float*)d_in[9];
    const float* W2r = (const float*)d_in[10];

    int n = in_sizes[3];   // y: [N]
    int e = in_sizes[1];   // edge_src: [E]

    const int smem1 = (128 * SWS + 128 * SAS) * 4;  // 104,448 B
    const int smem2 = (64 * SWS + 128 * SAS) * 4;   //  69,632 B
    cudaFuncSetAttribute(k_gemm1, cudaFuncAttributeMaxDynamicSharedMemorySize, smem1);
    cudaFuncSetAttribute(k_gemm2, cudaFuncAttributeMaxDynamicSharedMemorySize, smem2);

    void* pcounts;
    cudaGetSymbolAddress(&pcounts, g_counts);
    cudaMemsetAsync(pcounts, 0, (size_t)n * sizeof(int), 0);

    k_xhist<<<(n * 32 + 255) / 256, 256>>>((const float4*)x, n * 32, edst, e,
                                           W1l, W1r, W2l, W2r);
    k_offsets<<<(n + 255) / 256, 256>>>(n);
    k_scatter<<<(e + 255) / 256, 256>>>(esrc, edst, e);

    k_aggr_bf<<<(n + 7) / 8, 256>>>(n);
    k_gemm1<<<(n + 127) / 128, 256, smem1>>>(b1, n);
    k_gemm2<<<(n + 127) / 128, 256, smem2>>>(n);
    k_aggr_loss<<<(n + 7) / 8, 256>>>(b2, y, mask, n, (float*)d_out);
}